// round 8
// baseline (speedup 1.0000x reference)
#include <cuda_runtime.h>
#include <cstdint>

#define N_NODES 100000
#define N_FEAT  128
#define N_EDGES 1600000
#define SCAN_CHUNK 1024
#define NBLK ((N_NODES + SCAN_CHUNK - 1) / SCAN_CHUNK)   // 98

// Scratch (__device__ globals: allocation-free).
__device__ int   g_degi[N_NODES];
__device__ int   g_rowstart[N_NODES];
__device__ int   g_cursor[N_NODES];
__device__ int   g_bsum[128];
__device__ int   g_srcs[N_EDGES];
__device__ float g_dinv[N_NODES];
__device__ float g_Bfrag[16 * 32 * 16 * 2];          // [kc][lane][nc] float2 {hi0,hi1}
__device__ float g_xw[(size_t)N_NODES * N_FEAT];     // (x@W^T) * dinv[row]

__device__ __forceinline__ uint32_t tf32_rna(float v) {
    uint32_t r;
    asm("cvt.rna.tf32.f32 %0, %1;" : "=r"(r) : "f"(v));
    return r;
}

// ---------------------------------------------------------------------------
// 1) fused: zero degree counters + pack W hi-fragments, lane-major layout:
//    g_Bfrag[((kc*32 + lane)*16 + nc)] (float2) so a warp's 8 nc-frags per kc
//    are 64 contiguous bytes per lane (4x LDG.128 in the gemm).
__global__ void k_init_bpack(const float* __restrict__ W) {
    const int t = blockIdx.x * blockDim.x + threadIdx.x;
    if (t < N_NODES) g_degi[t] = 0;
    if (t < 16 * 16 * 32) {
        const int lane = t & 31;
        const int nc   = (t >> 5) & 15;
        const int kc   = t >> 9;
        const int k = kc * 8 + (lane & 3);
        const int n = nc * 8 + (lane >> 2);
        const uint32_t h0 = tf32_rna(W[n * N_FEAT + k]);      // W^T[k][n]
        const uint32_t h1 = tf32_rna(W[n * N_FEAT + k + 4]);
        reinterpret_cast<float2*>(g_Bfrag)[(kc * 32 + lane) * 16 + nc] =
            make_float2(__uint_as_float(h0), __uint_as_float(h1));
    }
}

// 2) degree count
__global__ void k_deg_count(const int* __restrict__ col) {
    int e = blockIdx.x * blockDim.x + threadIdx.x;
    if (e < N_EDGES) atomicAdd(&g_degi[col[e]], 1);
}

// 3) scan stage 1 (+ dinv)
__global__ void k_scan1() {
    __shared__ int sh[256];
    const int t = threadIdx.x;
    const int base = blockIdx.x * SCAN_CHUNK + t * 4;
    int v[4], s = 0;
    #pragma unroll
    for (int i = 0; i < 4; ++i) {
        int idx = base + i;
        v[i] = (idx < N_NODES) ? g_degi[idx] : 0;
        if (idx < N_NODES) g_dinv[idx] = rsqrtf((float)(v[i] + 1));
        s += v[i];
    }
    sh[t] = s; __syncthreads();
    #pragma unroll
    for (int off = 1; off < 256; off <<= 1) {
        int add = (t >= off) ? sh[t - off] : 0;
        __syncthreads();
        sh[t] += add;
        __syncthreads();
    }
    if (t == 255) g_bsum[blockIdx.x] = sh[255];
    int run = sh[t] - s;
    #pragma unroll
    for (int i = 0; i < 4; ++i) {
        int idx = base + i;
        if (idx < N_NODES) g_rowstart[idx] = run;
        run += v[i];
    }
}

// ---------------------------------------------------------------------------
#define MMA_TF32(acc, a0, a1, a2, a3, b0, b1)                                  \
    asm volatile("mma.sync.aligned.m16n8k8.row.col.f32.tf32.tf32.f32 "         \
                 "{%0,%1,%2,%3}, {%4,%5,%6,%7}, {%8,%9}, {%0,%1,%2,%3};"       \
                 : "+f"(acc[0]), "+f"(acc[1]), "+f"(acc[2]), "+f"(acc[3])      \
                 : "r"(a0), "r"(a1), "r"(a2), "r"(a3), "r"(b0), "r"(b1))

// 4) GEMM (profiled): g_xw = (x @ W^T) * dinv[row].  2-term tf32 split.
//    Block = 256 threads / 8 warps, tile 64 rows x 128 cols,
//    warp tile 16x64 (warps split N 2-way).
//    A pre-split hi/lo into fragment-layout smem [rb][kc][lane][reg]:
//    mainloop = 2 LDS.128 + 4 LDG.128 + 16 MMA per kc.
__global__ __launch_bounds__(256) void k_gemm(const float* __restrict__ x) {
    extern __shared__ float smem[];                    // hi[8192] ++ lo[8192]
    float* fhi = smem;
    float* flo = smem + 8192;
    const int t    = threadIdx.x;
    const int warp = t >> 5;
    const int lane = t & 31;
    const int row0  = blockIdx.x * 64;
    const int nrows = min(64, N_NODES - row0);

    // Staging: load x tile, split, scatter into fragment layout.
    // Element (r, k): rb=r>>4, rr=r&15, kc=k>>3, kk=k&7,
    //   frag lane = (rr&7)*4 + (k&3), reg = (rr>>3) + ((kk>>2)<<1)
    //   float idx = ((rb*16 + kc)*32 + lane)*4 + reg
    const float4* src = reinterpret_cast<const float4*>(x + (size_t)row0 * N_FEAT);
    for (int idx = t; idx < nrows * 32; idx += 256) {
        const int r  = idx >> 5, c4 = idx & 31;
        const float4 v = src[idx];
        const int rb = r >> 4, rr = r & 15;
        const int lbase = (rr & 7) * 4;
        const int rbit  = rr >> 3;
        #pragma unroll
        for (int i = 0; i < 4; ++i) {
            const int k  = c4 * 4 + i;
            const int kc = k >> 3, kk = k & 7;
            const int fi = ((rb * 16 + kc) * 32 + lbase + (k & 3)) * 4
                           + rbit + ((kk >> 2) << 1);
            const float val = (&v.x)[i];
            const uint32_t h = tf32_rna(val);
            fhi[fi] = __uint_as_float(h);
            flo[fi] = val - __uint_as_float(h);
        }
    }
    __syncthreads();

    const int rb  = (warp & 3);       // row block (16 rows)
    const int nc0 = (warp >> 2) * 8;  // nc range [nc0, nc0+8)

    float acc[8][4];
    #pragma unroll
    for (int j = 0; j < 8; ++j)
        acc[j][0] = acc[j][1] = acc[j][2] = acc[j][3] = 0.f;

    // A frag pointers (float4 units): index (rb*16 + kc)*32 + lane
    const float4* hfp = reinterpret_cast<const float4*>(fhi) + rb * 512 + lane;
    const float4* lfp = reinterpret_cast<const float4*>(flo) + rb * 512 + lane;
    // B: float4 idx = (kc*32 + lane)*8 + nc0/2 + j  (each float4 = 2 nc-frags)
    const float4* bp = reinterpret_cast<const float4*>(g_Bfrag)
                       + (size_t)lane * 8 + (nc0 >> 1);

    float4 bcur[4];
    #pragma unroll
    for (int j = 0; j < 4; ++j) bcur[j] = bp[j];

    #pragma unroll
    for (int kc = 0; kc < 16; ++kc) {
        const float4 ah = hfp[kc * 32];
        const float4 al = lfp[kc * 32];
        const uint32_t h0 = __float_as_uint(ah.x), h1 = __float_as_uint(ah.y);
        const uint32_t h2 = __float_as_uint(ah.z), h3 = __float_as_uint(ah.w);
        const uint32_t l0 = __float_as_uint(al.x), l1 = __float_as_uint(al.y);
        const uint32_t l2 = __float_as_uint(al.z), l3 = __float_as_uint(al.w);

        float4 bnxt[4];
        if (kc < 15) {
            #pragma unroll
            for (int j = 0; j < 4; ++j) bnxt[j] = bp[(kc + 1) * 256 + j];
        }

        #pragma unroll
        for (int j = 0; j < 4; ++j) {
            const uint32_t b0 = __float_as_uint(bcur[j].x);
            const uint32_t b1 = __float_as_uint(bcur[j].y);
            const uint32_t b2 = __float_as_uint(bcur[j].z);
            const uint32_t b3 = __float_as_uint(bcur[j].w);
            MMA_TF32(acc[2*j],     h0, h1, h2, h3, b0, b1);
            MMA_TF32(acc[2*j],     l0, l1, l2, l3, b0, b1);
            MMA_TF32(acc[2*j + 1], h0, h1, h2, h3, b2, b3);
            MMA_TF32(acc[2*j + 1], l0, l1, l2, l3, b2, b3);
        }
        if (kc < 15) {
            #pragma unroll
            for (int j = 0; j < 4; ++j) bcur[j] = bnxt[j];
        }
    }

    // Epilogue: C frag c0/c1 -> (row0+rb*16+g, col), c2/c3 -> (+8 rows)
    const int g  = lane >> 2;
    const int tg = lane & 3;
    const int r0 = row0 + rb * 16 + g;
    const int r1 = r0 + 8;
    const float d0 = (r0 < N_NODES) ? g_dinv[r0] : 0.f;
    const float d1 = (r1 < N_NODES) ? g_dinv[r1] : 0.f;
    #pragma unroll
    for (int j = 0; j < 8; ++j) {
        const int col = (nc0 + j) * 8 + tg * 2;
        if (r0 < N_NODES)
            *reinterpret_cast<float2*>(g_xw + (size_t)r0 * N_FEAT + col) =
                make_float2(acc[j][0] * d0, acc[j][1] * d0);
        if (r1 < N_NODES)
            *reinterpret_cast<float2*>(g_xw + (size_t)r1 * N_FEAT + col) =
                make_float2(acc[j][2] * d1, acc[j][3] * d1);
    }
}

// 5) fused scan stages 2+3
__global__ void k_scan23() {
    __shared__ int sh[128];
    const int t = threadIdx.x;
    int v = 0;
    if (t < 128) { v = (t < NBLK) ? g_bsum[t] : 0; sh[t] = v; }
    __syncthreads();
    #pragma unroll
    for (int off = 1; off < 128; off <<= 1) {
        int add = 0;
        if (t < 128 && t >= off) add = sh[t - off];
        __syncthreads();
        if (t < 128) sh[t] += add;
        __syncthreads();
    }
    if (t < 128) sh[t] -= v;
    __syncthreads();
    const int i = blockIdx.x * blockDim.x + t;
    if (i < N_NODES) {
        int rs = g_rowstart[i] + sh[i >> 10];
        g_rowstart[i] = rs;
        g_cursor[i]   = rs;
    }
}

// 6) bucket-fill
__global__ void k_fill(const int* __restrict__ ei) {
    int e = blockIdx.x * blockDim.x + threadIdx.x;
    if (e < N_EDGES) {
        int c = ei[N_EDGES + e];
        int pos = atomicAdd(&g_cursor[c], 1);
        g_srcs[pos] = ei[e];
    }
}

// ---------------------------------------------------------------------------
// 7) Pull aggregation: one warp per target node. xw pre-scaled by dinv[row].
__global__ __launch_bounds__(256) void k_gather(const float* __restrict__ b,
                                                float* __restrict__ out) {
    const int warp = (blockIdx.x * blockDim.x + threadIdx.x) >> 5;
    const int lane = threadIdx.x & 31;
    if (warp >= N_NODES) return;
    const int c = warp;

    const int base = g_rowstart[c];
    const int cnt  = g_degi[c];

    float4 a0 = make_float4(0.f,0.f,0.f,0.f), a1 = a0, a2 = a0, a3 = a0;
    const float4* xw = reinterpret_cast<const float4*>(g_xw);

    int i = 0;
    for (; i + 4 <= cnt; i += 4) {
        const int s0 = g_srcs[base + i + 0];
        const int s1 = g_srcs[base + i + 1];
        const int s2 = g_srcs[base + i + 2];
        const int s3 = g_srcs[base + i + 3];
        const float4 v0 = xw[(size_t)s0 * 32 + lane];
        const float4 v1 = xw[(size_t)s1 * 32 + lane];
        const float4 v2 = xw[(size_t)s2 * 32 + lane];
        const float4 v3 = xw[(size_t)s3 * 32 + lane];
        a0.x += v0.x; a0.y += v0.y; a0.z += v0.z; a0.w += v0.w;
        a1.x += v1.x; a1.y += v1.y; a1.z += v1.z; a1.w += v1.w;
        a2.x += v2.x; a2.y += v2.y; a2.z += v2.z; a2.w += v2.w;
        a3.x += v3.x; a3.y += v3.y; a3.z += v3.z; a3.w += v3.w;
    }
    for (; i < cnt; ++i) {
        const int s = g_srcs[base + i];
        const float4 v = xw[(size_t)s * 32 + lane];
        a0.x += v.x; a0.y += v.y; a0.z += v.z; a0.w += v.w;
    }

    const float4 self = xw[(size_t)c * 32 + lane];
    float4 acc = make_float4(a0.x + a1.x + a2.x + a3.x + self.x,
                             a0.y + a1.y + a2.y + a3.y + self.y,
                             a0.z + a1.z + a2.z + a3.z + self.z,
                             a0.w + a1.w + a2.w + a3.w + self.w);
    const float nc = g_dinv[c];
    const float4 bv = reinterpret_cast<const float4*>(b)[lane];
    reinterpret_cast<float4*>(out + (size_t)c * N_FEAT)[lane] =
        make_float4(acc.x * nc + bv.x, acc.y * nc + bv.y,
                    acc.z * nc + bv.z, acc.w * nc + bv.w);
}

// ---------------------------------------------------------------------------
extern "C" void kernel_launch(void* const* d_in, const int* in_sizes, int n_in,
                              void* d_out, int out_size) {
    const float* x  = (const float*)d_in[0];
    const int*   ei = (const int*)  d_in[1];
    const float* W  = (const float*)d_in[2];
    const float* b  = (const float*)d_in[3];
    float* out = (float*)d_out;

    static bool attr_set = false;
    if (!attr_set) {
        cudaFuncSetAttribute(k_gemm, cudaFuncAttributeMaxDynamicSharedMemorySize,
                             65536);
        attr_set = true;
    }

    k_init_bpack<<<(N_NODES + 255) / 256, 256>>>(W);               // 1
    k_deg_count <<<(N_EDGES + 255) / 256, 256>>>(ei + N_EDGES);    // 2
    k_scan1     <<<NBLK, 256>>>();                                 // 3 (dinv ready)
    k_gemm      <<<(N_NODES + 63) / 64, 256, 65536>>>(x);          // 4 (profiled)
    k_scan23    <<<(N_NODES + 255) / 256, 256>>>();                // 5
    k_fill      <<<(N_EDGES + 255) / 256, 256>>>(ei);              // 6
    k_gather    <<<(N_NODES * 32 + 255) / 256, 256>>>(b, out);     // 7
}

// round 9
// speedup vs baseline: 1.6172x; 1.6172x over previous
#include <cuda_runtime.h>
#include <cstdint>

#define N_NODES 100000
#define N_FEAT  128
#define N_EDGES 1600000
#define SCAN_CHUNK 1024
#define NBLK ((N_NODES + SCAN_CHUNK - 1) / SCAN_CHUNK)   // 98

// Scratch (__device__ globals: allocation-free).
__device__ int   g_degi[N_NODES];
__device__ int   g_rowstart[N_NODES];
__device__ int   g_cursor[N_NODES];
__device__ int   g_bsum[128];
__device__ int   g_srcs[N_EDGES];
__device__ float g_dinv[N_NODES];
__device__ float g_Bfrag[16 * 8 * 32 * 4];           // [kc][jj][lane] float4
__device__ float g_xw[(size_t)N_NODES * N_FEAT];     // (x@W^T) * dinv[row]

__device__ __forceinline__ uint32_t tf32_rna(float v) {
    uint32_t r;
    asm("cvt.rna.tf32.f32 %0, %1;" : "=r"(r) : "f"(v));
    return r;
}

// ---------------------------------------------------------------------------
// 1) fused: zero degree counters + pack W hi-fragments.
//    Layout: float4 at ((kc*8 + jj)*32 + lane) holds
//    {b(2jj)hi0, b(2jj)hi1, b(2jj+1)hi0, b(2jj+1)hi1} — lane-coalesced loads.
__global__ void k_init_bpack(const float* __restrict__ W) {
    const int t = blockIdx.x * blockDim.x + threadIdx.x;
    if (t < N_NODES) g_degi[t] = 0;
    if (t < 16 * 16 * 32) {
        const int lane = t & 31;
        const int nc   = (t >> 5) & 15;
        const int kc   = t >> 9;
        const int k = kc * 8 + (lane & 3);
        const int n = nc * 8 + (lane >> 2);
        const uint32_t h0 = tf32_rna(W[n * N_FEAT + k]);      // W^T[k][n]
        const uint32_t h1 = tf32_rna(W[n * N_FEAT + k + 4]);
        const int f2i = ((kc * 8 + (nc >> 1)) * 32 + lane) * 2 + (nc & 1);
        reinterpret_cast<float2*>(g_Bfrag)[f2i] =
            make_float2(__uint_as_float(h0), __uint_as_float(h1));
    }
}

// 2) degree count
__global__ void k_deg_count(const int* __restrict__ col) {
    int e = blockIdx.x * blockDim.x + threadIdx.x;
    if (e < N_EDGES) atomicAdd(&g_degi[col[e]], 1);
}

// 3) scan stage 1 (+ dinv)
__global__ void k_scan1() {
    __shared__ int sh[256];
    const int t = threadIdx.x;
    const int base = blockIdx.x * SCAN_CHUNK + t * 4;
    int v[4], s = 0;
    #pragma unroll
    for (int i = 0; i < 4; ++i) {
        int idx = base + i;
        v[i] = (idx < N_NODES) ? g_degi[idx] : 0;
        if (idx < N_NODES) g_dinv[idx] = rsqrtf((float)(v[i] + 1));
        s += v[i];
    }
    sh[t] = s; __syncthreads();
    #pragma unroll
    for (int off = 1; off < 256; off <<= 1) {
        int add = (t >= off) ? sh[t - off] : 0;
        __syncthreads();
        sh[t] += add;
        __syncthreads();
    }
    if (t == 255) g_bsum[blockIdx.x] = sh[255];
    int run = sh[t] - s;
    #pragma unroll
    for (int i = 0; i < 4; ++i) {
        int idx = base + i;
        if (idx < N_NODES) g_rowstart[idx] = run;
        run += v[i];
    }
}

// ---------------------------------------------------------------------------
#define MMA_TF32(acc, a0, a1, a2, a3, b0, b1)                                  \
    asm volatile("mma.sync.aligned.m16n8k8.row.col.f32.tf32.tf32.f32 "         \
                 "{%0,%1,%2,%3}, {%4,%5,%6,%7}, {%8,%9}, {%0,%1,%2,%3};"       \
                 : "+f"(acc[0]), "+f"(acc[1]), "+f"(acc[2]), "+f"(acc[3])      \
                 : "r"(a0), "r"(a1), "r"(a2), "r"(a3), "r"(b0), "r"(b1))

// 4) GEMM (profiled): g_xw = (x @ W^T) * dinv[row].  2-term tf32 split.
//    Block = 256 threads / 8 warps, tile 64x128, warp tile 16x64.
//    Staging: item = (rb, kc, lane); 4 LDG.32 from x, hi/lo split in regs,
//    one STS.128 each into fragment-layout smem (lane stride 16B, no conflicts).
//    Mainloop per kc: 2 LDS.128 (A hi/lo) + 4 LDG.128 (B, coalesced) + 16 MMA.
__global__ __launch_bounds__(256) void k_gemm(const float* __restrict__ x) {
    extern __shared__ float smem[];                    // fhi[8192] ++ flo[8192]
    float4* fhi4 = reinterpret_cast<float4*>(smem);
    float4* flo4 = fhi4 + 2048;
    const int t    = threadIdx.x;
    const int warp = t >> 5;
    const int lane = t & 31;
    const int row0 = blockIdx.x * 64;

    // ---- staging: 64 tiles of (rb, kc); warp w handles tiles w, w+8, ... ----
    #pragma unroll
    for (int i = 0; i < 8; ++i) {
        const int tile = warp + 8 * i;          // 0..63
        const int rbt  = tile >> 4;             // rb 0..3
        const int kct  = tile & 15;             // kc 0..15
        const int row  = row0 + rbt * 16 + (lane >> 2);
        const int k0   = kct * 8 + (lane & 3);
        float a0 = 0.f, a1 = 0.f, a2 = 0.f, a3 = 0.f;
        if (row < N_NODES) {
            a0 = x[(size_t)row * N_FEAT + k0];
            a2 = x[(size_t)row * N_FEAT + k0 + 4];
        }
        if (row + 8 < N_NODES) {
            a1 = x[(size_t)(row + 8) * N_FEAT + k0];
            a3 = x[(size_t)(row + 8) * N_FEAT + k0 + 4];
        }
        const uint32_t h0 = tf32_rna(a0), h1 = tf32_rna(a1);
        const uint32_t h2 = tf32_rna(a2), h3 = tf32_rna(a3);
        fhi4[tile * 32 + lane] = make_float4(
            __uint_as_float(h0), __uint_as_float(h1),
            __uint_as_float(h2), __uint_as_float(h3));
        flo4[tile * 32 + lane] = make_float4(
            a0 - __uint_as_float(h0), a1 - __uint_as_float(h1),
            a2 - __uint_as_float(h2), a3 - __uint_as_float(h3));
    }
    __syncthreads();

    const int rb  = (warp & 3);       // row block (16 rows)
    const int nc0 = (warp >> 2) * 8;  // nc range [nc0, nc0+8)

    float acc[8][4];
    #pragma unroll
    for (int j = 0; j < 8; ++j)
        acc[j][0] = acc[j][1] = acc[j][2] = acc[j][3] = 0.f;

    // A frag pointers: float4 at (rb*16 + kc)*32 + lane
    const float4* hfp = fhi4 + rb * 512 + lane;
    const float4* lfp = flo4 + rb * 512 + lane;
    // B: float4 at (kc*8 + jj)*32 + lane, warp uses jj = nc0/2 + j
    const float4* bp = reinterpret_cast<const float4*>(g_Bfrag)
                       + ((nc0 >> 1) * 32 + lane);

    float4 bcur[4];
    #pragma unroll
    for (int j = 0; j < 4; ++j) bcur[j] = bp[j * 32];

    #pragma unroll
    for (int kc = 0; kc < 16; ++kc) {
        const float4 ah = hfp[kc * 32];
        const float4 al = lfp[kc * 32];
        const uint32_t h0 = __float_as_uint(ah.x), h1 = __float_as_uint(ah.y);
        const uint32_t h2 = __float_as_uint(ah.z), h3 = __float_as_uint(ah.w);
        const uint32_t l0 = __float_as_uint(al.x), l1 = __float_as_uint(al.y);
        const uint32_t l2 = __float_as_uint(al.z), l3 = __float_as_uint(al.w);

        float4 bnxt[4];
        if (kc < 15) {
            #pragma unroll
            for (int j = 0; j < 4; ++j) bnxt[j] = bp[(kc + 1) * 256 + j * 32];
        }

        #pragma unroll
        for (int j = 0; j < 4; ++j) {
            const uint32_t b0 = __float_as_uint(bcur[j].x);
            const uint32_t b1 = __float_as_uint(bcur[j].y);
            const uint32_t b2 = __float_as_uint(bcur[j].z);
            const uint32_t b3 = __float_as_uint(bcur[j].w);
            MMA_TF32(acc[2*j],     h0, h1, h2, h3, b0, b1);
            MMA_TF32(acc[2*j],     l0, l1, l2, l3, b0, b1);
            MMA_TF32(acc[2*j + 1], h0, h1, h2, h3, b2, b3);
            MMA_TF32(acc[2*j + 1], l0, l1, l2, l3, b2, b3);
        }
        if (kc < 15) {
            #pragma unroll
            for (int j = 0; j < 4; ++j) bcur[j] = bnxt[j];
        }
    }

    // Epilogue: C frag c0/c1 -> (row0+rb*16+g, col), c2/c3 -> (+8 rows)
    const int g  = lane >> 2;
    const int tg = lane & 3;
    const int r0 = row0 + rb * 16 + g;
    const int r1 = r0 + 8;
    const float d0 = (r0 < N_NODES) ? g_dinv[r0] : 0.f;
    const float d1 = (r1 < N_NODES) ? g_dinv[r1] : 0.f;
    #pragma unroll
    for (int j = 0; j < 8; ++j) {
        const int col = (nc0 + j) * 8 + tg * 2;
        if (r0 < N_NODES)
            *reinterpret_cast<float2*>(g_xw + (size_t)r0 * N_FEAT + col) =
                make_float2(acc[j][0] * d0, acc[j][1] * d0);
        if (r1 < N_NODES)
            *reinterpret_cast<float2*>(g_xw + (size_t)r1 * N_FEAT + col) =
                make_float2(acc[j][2] * d1, acc[j][3] * d1);
    }
}

// 5) fused scan stages 2+3
__global__ void k_scan23() {
    __shared__ int sh[128];
    const int t = threadIdx.x;
    int v = 0;
    if (t < 128) { v = (t < NBLK) ? g_bsum[t] : 0; sh[t] = v; }
    __syncthreads();
    #pragma unroll
    for (int off = 1; off < 128; off <<= 1) {
        int add = 0;
        if (t < 128 && t >= off) add = sh[t - off];
        __syncthreads();
        if (t < 128) sh[t] += add;
        __syncthreads();
    }
    if (t < 128) sh[t] -= v;
    __syncthreads();
    const int i = blockIdx.x * blockDim.x + t;
    if (i < N_NODES) {
        int rs = g_rowstart[i] + sh[i >> 10];
        g_rowstart[i] = rs;
        g_cursor[i]   = rs;
    }
}

// 6) bucket-fill
__global__ void k_fill(const int* __restrict__ ei) {
    int e = blockIdx.x * blockDim.x + threadIdx.x;
    if (e < N_EDGES) {
        int c = ei[N_EDGES + e];
        int pos = atomicAdd(&g_cursor[c], 1);
        g_srcs[pos] = ei[e];
    }
}

// ---------------------------------------------------------------------------
// 7) Pull aggregation: one warp per target node. xw pre-scaled by dinv[row].
__global__ __launch_bounds__(256) void k_gather(const float* __restrict__ b,
                                                float* __restrict__ out) {
    const int warp = (blockIdx.x * blockDim.x + threadIdx.x) >> 5;
    const int lane = threadIdx.x & 31;
    if (warp >= N_NODES) return;
    const int c = warp;

    const int base = g_rowstart[c];
    const int cnt  = g_degi[c];

    float4 a0 = make_float4(0.f,0.f,0.f,0.f), a1 = a0, a2 = a0, a3 = a0;
    const float4* xw = reinterpret_cast<const float4*>(g_xw);

    int i = 0;
    for (; i + 4 <= cnt; i += 4) {
        const int s0 = g_srcs[base + i + 0];
        const int s1 = g_srcs[base + i + 1];
        const int s2 = g_srcs[base + i + 2];
        const int s3 = g_srcs[base + i + 3];
        const float4 v0 = xw[(size_t)s0 * 32 + lane];
        const float4 v1 = xw[(size_t)s1 * 32 + lane];
        const float4 v2 = xw[(size_t)s2 * 32 + lane];
        const float4 v3 = xw[(size_t)s3 * 32 + lane];
        a0.x += v0.x; a0.y += v0.y; a0.z += v0.z; a0.w += v0.w;
        a1.x += v1.x; a1.y += v1.y; a1.z += v1.z; a1.w += v1.w;
        a2.x += v2.x; a2.y += v2.y; a2.z += v2.z; a2.w += v2.w;
        a3.x += v3.x; a3.y += v3.y; a3.z += v3.z; a3.w += v3.w;
    }
    for (; i < cnt; ++i) {
        const int s = g_srcs[base + i];
        const float4 v = xw[(size_t)s * 32 + lane];
        a0.x += v.x; a0.y += v.y; a0.z += v.z; a0.w += v.w;
    }

    const float4 self = xw[(size_t)c * 32 + lane];
    float4 acc = make_float4(a0.x + a1.x + a2.x + a3.x + self.x,
                             a0.y + a1.y + a2.y + a3.y + self.y,
                             a0.z + a1.z + a2.z + a3.z + self.z,
                             a0.w + a1.w + a2.w + a3.w + self.w);
    const float nc = g_dinv[c];
    const float4 bv = reinterpret_cast<const float4*>(b)[lane];
    reinterpret_cast<float4*>(out + (size_t)c * N_FEAT)[lane] =
        make_float4(acc.x * nc + bv.x, acc.y * nc + bv.y,
                    acc.z * nc + bv.z, acc.w * nc + bv.w);
}

// ---------------------------------------------------------------------------
extern "C" void kernel_launch(void* const* d_in, const int* in_sizes, int n_in,
                              void* d_out, int out_size) {
    const float* x  = (const float*)d_in[0];
    const int*   ei = (const int*)  d_in[1];
    const float* W  = (const float*)d_in[2];
    const float* b  = (const float*)d_in[3];
    float* out = (float*)d_out;

    static bool attr_set = false;
    if (!attr_set) {
        cudaFuncSetAttribute(k_gemm, cudaFuncAttributeMaxDynamicSharedMemorySize,
                             65536);
        attr_set = true;
    }

    k_init_bpack<<<(N_NODES + 255) / 256, 256>>>(W);               // 1
    k_deg_count <<<(N_EDGES + 255) / 256, 256>>>(ei + N_EDGES);    // 2
    k_scan1     <<<NBLK, 256>>>();                                 // 3 (dinv ready)
    k_gemm      <<<(N_NODES + 63) / 64, 256, 65536>>>(x);          // 4 (profiled)
    k_scan23    <<<(N_NODES + 255) / 256, 256>>>();                // 5
    k_fill      <<<(N_EDGES + 255) / 256, 256>>>(ei);              // 6
    k_gather    <<<(N_NODES * 32 + 255) / 256, 256>>>(b, out);     // 7
}

// round 10
// speedup vs baseline: 1.9203x; 1.1874x over previous
#include <cuda_runtime.h>
#include <cuda_fp16.h>
#include <cstdint>

#define N_NODES 100000
#define N_FEAT  128
#define N_EDGES 1600000
#define SCAN_CHUNK 1024
#define NBLK ((N_NODES + SCAN_CHUNK - 1) / SCAN_CHUNK)   // 98

// Scratch (__device__ globals: allocation-free).
__device__ int    g_degi[N_NODES];
__device__ int    g_rowstart[N_NODES];
__device__ int    g_cursor[N_NODES];
__device__ int    g_bsum[128];
__device__ int    g_srcs[N_EDGES];
__device__ float  g_dinv[N_NODES];
__device__ float  g_Bfrag[16 * 16 * 32 * 2];         // W hi fragments {hi0,hi1}
__device__ __half g_xwh[(size_t)N_NODES * N_FEAT];   // (x@W^T)*dinv[row], fp16

__device__ __forceinline__ uint32_t tf32_rna(float v) {
    uint32_t r;
    asm("cvt.rna.tf32.f32 %0, %1;" : "=r"(r) : "f"(v));
    return r;
}

// ---------------------------------------------------------------------------
// 1) fused: zero degree counters + pack W hi-fragments (R7 layout)
//    B frag (k8 x n8, col-major): b0 -> (k=lane%4, n=lane/4), b1 -> (k+4, n)
__global__ void k_init_bpack(const float* __restrict__ W) {
    const int t = blockIdx.x * blockDim.x + threadIdx.x;
    if (t < N_NODES) g_degi[t] = 0;
    if (t < 16 * 16 * 32) {
        const int lane = t & 31;
        const int nc   = (t >> 5) & 15;
        const int kc   = t >> 9;
        const int k = kc * 8 + (lane & 3);
        const int n = nc * 8 + (lane >> 2);
        const uint32_t h0 = tf32_rna(W[n * N_FEAT + k]);      // W^T[k][n]
        const uint32_t h1 = tf32_rna(W[n * N_FEAT + k + 4]);
        reinterpret_cast<float2*>(g_Bfrag)[t] =
            make_float2(__uint_as_float(h0), __uint_as_float(h1));
    }
}

// 2) degree count
__global__ void k_deg_count(const int* __restrict__ col) {
    int e = blockIdx.x * blockDim.x + threadIdx.x;
    if (e < N_EDGES) atomicAdd(&g_degi[col[e]], 1);
}

// 3) scan stage 1 (+ dinv)
__global__ void k_scan1() {
    __shared__ int sh[256];
    const int t = threadIdx.x;
    const int base = blockIdx.x * SCAN_CHUNK + t * 4;
    int v[4], s = 0;
    #pragma unroll
    for (int i = 0; i < 4; ++i) {
        int idx = base + i;
        v[i] = (idx < N_NODES) ? g_degi[idx] : 0;
        if (idx < N_NODES) g_dinv[idx] = rsqrtf((float)(v[i] + 1));
        s += v[i];
    }
    sh[t] = s; __syncthreads();
    #pragma unroll
    for (int off = 1; off < 256; off <<= 1) {
        int add = (t >= off) ? sh[t - off] : 0;
        __syncthreads();
        sh[t] += add;
        __syncthreads();
    }
    if (t == 255) g_bsum[blockIdx.x] = sh[255];
    int run = sh[t] - s;
    #pragma unroll
    for (int i = 0; i < 4; ++i) {
        int idx = base + i;
        if (idx < N_NODES) g_rowstart[idx] = run;
        run += v[i];
    }
}

// ---------------------------------------------------------------------------
#define MMA_TF32(acc, a0, a1, a2, a3, b0, b1)                                  \
    asm volatile("mma.sync.aligned.m16n8k8.row.col.f32.tf32.tf32.f32 "         \
                 "{%0,%1,%2,%3}, {%4,%5,%6,%7}, {%8,%9}, {%0,%1,%2,%3};"       \
                 : "+f"(acc[0]), "+f"(acc[1]), "+f"(acc[2]), "+f"(acc[3])      \
                 : "r"(a0), "r"(a1), "r"(a2), "r"(a3), "r"(b0), "r"(b1))

// 4) GEMM (profiled, R7 mainloop verbatim): g_xwh = half(x @ W^T * dinv[row]).
//    2-term tf32 split. Block = 256 threads / 8 warps, warp tile 16x64.
__global__ __launch_bounds__(256) void k_gemm(const float* __restrict__ x) {
    __shared__ float xs[64][132];                      // pad 132: conflict-free
    const int t    = threadIdx.x;
    const int warp = t >> 5;
    const int lane = t & 31;
    const int row0  = blockIdx.x * 64;
    const int nrows = min(64, N_NODES - row0);

    const float4* src = reinterpret_cast<const float4*>(x + (size_t)row0 * N_FEAT);
    for (int idx = t; idx < nrows * 32; idx += 256) {
        const int r = idx >> 5, c4 = idx & 31;
        *reinterpret_cast<float4*>(&xs[r][c4 * 4]) = src[idx];
    }
    __syncthreads();

    const int g   = lane >> 2;        // group id 0..7
    const int tg  = lane & 3;         // thread-in-group 0..3
    const int rb  = (warp & 3) * 16;  // row block within tile
    const int nc0 = (warp >> 2) * 8;  // nc range [nc0, nc0+8)

    float acc[8][4];
    #pragma unroll
    for (int j = 0; j < 8; ++j)
        acc[j][0] = acc[j][1] = acc[j][2] = acc[j][3] = 0.f;

    const float2* bptr = reinterpret_cast<const float2*>(g_Bfrag) + nc0 * 32 + lane;

    float2 bcur[8];
    #pragma unroll
    for (int j = 0; j < 8; ++j) bcur[j] = bptr[j * 32];

    #pragma unroll
    for (int kc = 0; kc < 16; ++kc) {
        const int k0 = kc * 8;
        const float ar0 = xs[rb + g][k0 + tg];
        const float ar1 = xs[rb + g + 8][k0 + tg];
        const float ar2 = xs[rb + g][k0 + tg + 4];
        const float ar3 = xs[rb + g + 8][k0 + tg + 4];
        const uint32_t h0 = tf32_rna(ar0), h1 = tf32_rna(ar1);
        const uint32_t h2 = tf32_rna(ar2), h3 = tf32_rna(ar3);
        const uint32_t l0 = __float_as_uint(ar0 - __uint_as_float(h0));
        const uint32_t l1 = __float_as_uint(ar1 - __uint_as_float(h1));
        const uint32_t l2 = __float_as_uint(ar2 - __uint_as_float(h2));
        const uint32_t l3 = __float_as_uint(ar3 - __uint_as_float(h3));

        float2 bnxt[8];
        if (kc < 15) {
            #pragma unroll
            for (int j = 0; j < 8; ++j) bnxt[j] = bptr[(kc + 1) * 512 + j * 32];
        }

        #pragma unroll
        for (int j = 0; j < 8; ++j) {
            const uint32_t bh0 = __float_as_uint(bcur[j].x);
            const uint32_t bh1 = __float_as_uint(bcur[j].y);
            MMA_TF32(acc[j], h0, h1, h2, h3, bh0, bh1);   // hi*hi
            MMA_TF32(acc[j], l0, l1, l2, l3, bh0, bh1);   // lo*hi
        }
        if (kc < 15) {
            #pragma unroll
            for (int j = 0; j < 8; ++j) bcur[j] = bnxt[j];
        }
    }

    // Epilogue: scale by dinv and store packed half2 (col, col+1 adjacent).
    const int r0 = row0 + rb + g;
    const int r1 = r0 + 8;
    const float d0 = (r0 < N_NODES) ? g_dinv[r0] : 0.f;
    const float d1 = (r1 < N_NODES) ? g_dinv[r1] : 0.f;
    #pragma unroll
    for (int j = 0; j < 8; ++j) {
        const int col = (nc0 + j) * 8 + tg * 2;
        if (r0 < N_NODES)
            *reinterpret_cast<__half2*>(&g_xwh[(size_t)r0 * N_FEAT + col]) =
                __floats2half2_rn(acc[j][0] * d0, acc[j][1] * d0);
        if (r1 < N_NODES)
            *reinterpret_cast<__half2*>(&g_xwh[(size_t)r1 * N_FEAT + col]) =
                __floats2half2_rn(acc[j][2] * d1, acc[j][3] * d1);
    }
}

// 5) fused scan stages 2+3
__global__ void k_scan23() {
    __shared__ int sh[128];
    const int t = threadIdx.x;
    int v = 0;
    if (t < 128) { v = (t < NBLK) ? g_bsum[t] : 0; sh[t] = v; }
    __syncthreads();
    #pragma unroll
    for (int off = 1; off < 128; off <<= 1) {
        int add = 0;
        if (t < 128 && t >= off) add = sh[t - off];
        __syncthreads();
        if (t < 128) sh[t] += add;
        __syncthreads();
    }
    if (t < 128) sh[t] -= v;
    __syncthreads();
    const int i = blockIdx.x * blockDim.x + t;
    if (i < N_NODES) {
        int rs = g_rowstart[i] + sh[i >> 10];
        g_rowstart[i] = rs;
        g_cursor[i]   = rs;
    }
}

// 6) bucket-fill
__global__ void k_fill(const int* __restrict__ ei) {
    int e = blockIdx.x * blockDim.x + threadIdx.x;
    if (e < N_EDGES) {
        int c = ei[N_EDGES + e];
        int pos = atomicAdd(&g_cursor[c], 1);
        g_srcs[pos] = ei[e];
    }
}

// ---------------------------------------------------------------------------
// 7) Pull aggregation: one warp per target node. fp16 rows (256B each, half
//    the L2 traffic), fp32 accumulation. Lane covers cols [lane*4, lane*4+4).
__global__ __launch_bounds__(256) void k_gather(const float* __restrict__ b,
                                                float* __restrict__ out) {
    const int warp = (blockIdx.x * blockDim.x + threadIdx.x) >> 5;
    const int lane = threadIdx.x & 31;
    if (warp >= N_NODES) return;
    const int c = warp;

    const int base = g_rowstart[c];
    const int cnt  = g_degi[c];

    float4 a0 = make_float4(0.f,0.f,0.f,0.f), a1 = a0, a2 = a0, a3 = a0;
    const uint2* xw = reinterpret_cast<const uint2*>(g_xwh);   // 8B = 4 halves

    int i = 0;
    for (; i + 4 <= cnt; i += 4) {
        const int s0 = g_srcs[base + i + 0];
        const int s1 = g_srcs[base + i + 1];
        const int s2 = g_srcs[base + i + 2];
        const int s3 = g_srcs[base + i + 3];
        const uint2 v0 = xw[(size_t)s0 * 32 + lane];
        const uint2 v1 = xw[(size_t)s1 * 32 + lane];
        const uint2 v2 = xw[(size_t)s2 * 32 + lane];
        const uint2 v3 = xw[(size_t)s3 * 32 + lane];
        {
            const float2 p = __half22float2(*(const __half2*)&v0.x);
            const float2 q = __half22float2(*(const __half2*)&v0.y);
            a0.x += p.x; a0.y += p.y; a0.z += q.x; a0.w += q.y;
        }
        {
            const float2 p = __half22float2(*(const __half2*)&v1.x);
            const float2 q = __half22float2(*(const __half2*)&v1.y);
            a1.x += p.x; a1.y += p.y; a1.z += q.x; a1.w += q.y;
        }
        {
            const float2 p = __half22float2(*(const __half2*)&v2.x);
            const float2 q = __half22float2(*(const __half2*)&v2.y);
            a2.x += p.x; a2.y += p.y; a2.z += q.x; a2.w += q.y;
        }
        {
            const float2 p = __half22float2(*(const __half2*)&v3.x);
            const float2 q = __half22float2(*(const __half2*)&v3.y);
            a3.x += p.x; a3.y += p.y; a3.z += q.x; a3.w += q.y;
        }
    }
    for (; i < cnt; ++i) {
        const int s = g_srcs[base + i];
        const uint2 v = xw[(size_t)s * 32 + lane];
        const float2 p = __half22float2(*(const __half2*)&v.x);
        const float2 q = __half22float2(*(const __half2*)&v.y);
        a0.x += p.x; a0.y += p.y; a0.z += q.x; a0.w += q.y;
    }

    const uint2 vs = xw[(size_t)c * 32 + lane];
    const float2 sp = __half22float2(*(const __half2*)&vs.x);
    const float2 sq = __half22float2(*(const __half2*)&vs.y);
    float4 acc = make_float4(a0.x + a1.x + a2.x + a3.x + sp.x,
                             a0.y + a1.y + a2.y + a3.y + sp.y,
                             a0.z + a1.z + a2.z + a3.z + sq.x,
                             a0.w + a1.w + a2.w + a3.w + sq.y);
    const float nc = g_dinv[c];
    const float4 bv = reinterpret_cast<const float4*>(b)[lane];
    reinterpret_cast<float4*>(out + (size_t)c * N_FEAT)[lane] =
        make_float4(acc.x * nc + bv.x, acc.y * nc + bv.y,
                    acc.z * nc + bv.z, acc.w * nc + bv.w);
}

// ---------------------------------------------------------------------------
extern "C" void kernel_launch(void* const* d_in, const int* in_sizes, int n_in,
                              void* d_out, int out_size) {
    const float* x  = (const float*)d_in[0];
    const int*   ei = (const int*)  d_in[1];
    const float* W  = (const float*)d_in[2];
    const float* b  = (const float*)d_in[3];
    float* out = (float*)d_out;

    k_init_bpack<<<(N_NODES + 255) / 256, 256>>>(W);               // 1
    k_deg_count <<<(N_EDGES + 255) / 256, 256>>>(ei + N_EDGES);    // 2
    k_scan1     <<<NBLK, 256>>>();                                 // 3 (dinv ready)
    k_gemm      <<<(N_NODES + 63) / 64, 256>>>(x);                 // 4 (profiled)
    k_scan23    <<<(N_NODES + 255) / 256, 256>>>();                // 5
    k_fill      <<<(N_EDGES + 255) / 256, 256>>>(ei);              // 6
    k_gather    <<<(N_NODES * 32 + 255) / 256, 256>>>(b, out);     // 7
}